// round 2
// baseline (speedup 1.0000x reference)
#include <cuda_runtime.h>
#include <math.h>

#define BATCH 2
#define SEQ   2048
#define DM    1024
#define NH    16
#define HW    64
#define SM_SCALE 0.125f   // 1/sqrt(64)

// Scratch for projected Q/K/V in [B, H, S, hw] layout (16 MB each).
__device__ float g_q[BATCH*NH*SEQ*HW];
__device__ float g_k[BATCH*NH*SEQ*HW];
__device__ float g_v[BATCH*NH*SEQ*HW];

// ---------------------------------------------------------------------------
// Projection GEMM: out[m, n] = sum_k X[m,k] * W[n,k]   (x @ W^T)
// M = B*S = 4096, N = D = 1024, K = D = 1024.
// BM=BN=64, BK=16, 256 threads, 4x4 micro-tile per thread.
// ---------------------------------------------------------------------------
__global__ __launch_bounds__(256) void proj_kernel(
    const float* __restrict__ xq, const float* __restrict__ xk, const float* __restrict__ xv,
    const float* __restrict__ wq, const float* __restrict__ wk, const float* __restrict__ wv)
{
    const int z = blockIdx.z;
    const float* X = (z == 0) ? xq : (z == 1) ? xk : xv;
    const float* W = (z == 0) ? wq : (z == 1) ? wk : wv;
    float*       O = (z == 0) ? g_q : (z == 1) ? g_k : g_v;

    __shared__ float As[16][64];   // [k][m]
    __shared__ float Bs[16][64];   // [k][n]

    const int tid = threadIdx.x;
    const int tx  = tid & 15;       // n-group
    const int ty  = tid >> 4;       // m-group
    const int m0  = blockIdx.y * 64;
    const int n0  = blockIdx.x * 64;

    const int lrow = tid >> 2;      // 0..63
    const int lcg  = tid & 3;       // float4 group within 16-wide k tile

    const float4* X4 = (const float4*)X;
    const float4* W4 = (const float4*)W;

    float acc[4][4];
#pragma unroll
    for (int i = 0; i < 4; i++)
#pragma unroll
        for (int j = 0; j < 4; j++) acc[i][j] = 0.0f;

    for (int k0 = 0; k0 < DM; k0 += 16) {
        float4 a = X4[(size_t)(m0 + lrow) * (DM/4) + (k0 >> 2) + lcg];
        float4 b = W4[(size_t)(n0 + lrow) * (DM/4) + (k0 >> 2) + lcg];
        As[lcg*4+0][lrow] = a.x; As[lcg*4+1][lrow] = a.y;
        As[lcg*4+2][lrow] = a.z; As[lcg*4+3][lrow] = a.w;
        Bs[lcg*4+0][lrow] = b.x; Bs[lcg*4+1][lrow] = b.y;
        Bs[lcg*4+2][lrow] = b.z; Bs[lcg*4+3][lrow] = b.w;
        __syncthreads();

#pragma unroll
        for (int kk = 0; kk < 16; kk++) {
            float4 av = ((const float4*)As[kk])[ty];
            float4 bv = ((const float4*)Bs[kk])[tx];
            float aa[4] = {av.x, av.y, av.z, av.w};
            float bb[4] = {bv.x, bv.y, bv.z, bv.w};
#pragma unroll
            for (int i = 0; i < 4; i++)
#pragma unroll
                for (int j = 0; j < 4; j++)
                    acc[i][j] += aa[i] * bb[j];
        }
        __syncthreads();
    }

    // Store into [B, H, S, hw] layout.
#pragma unroll
    for (int i = 0; i < 4; i++) {
        int m  = m0 + ty * 4 + i;
        int bb = m >> 11;             // m / SEQ
        int ss = m & (SEQ - 1);
#pragma unroll
        for (int j = 0; j < 4; j++) {
            int n  = n0 + tx * 4 + j;
            int hh = n >> 6;          // n / HW
            int dd = n & 63;
            O[(((size_t)(bb * NH + hh)) * SEQ + ss) * HW + dd] = acc[i][j];
        }
    }
}

// ---------------------------------------------------------------------------
// Flash attention with causal mask + ALiBi.
// grid = (S/64, B*H), block = 256 (8 warps). Warp w owns q-rows [8w, 8w+8);
// lane owns columns {lane, lane+32} of S-tile and dims {lane, lane+32} of O.
// Dynamic smem: Qs[64][64], Ks[64][68], Vs[64][68], Ps[64][68]  (67 KB).
// ---------------------------------------------------------------------------
__global__ __launch_bounds__(256) void attn_kernel(float* __restrict__ out)
{
    extern __shared__ float smem[];
    float* Qs = smem;                 // 4096 floats
    float* Ks = smem + 4096;          // 4352 floats (64 x 68)
    float* Vs = Ks + 4352;            // 4352 floats
    float* Ps = Vs + 4352;            // 4352 floats

    const int bh = blockIdx.y;
    const int b  = bh >> 4;
    const int h  = bh & 15;
    const int qt = blockIdx.x;
    const int q0 = qt * 64;

    const float4* Q4 = (const float4*)(g_q + (size_t)bh * SEQ * HW);
    const float4* K4 = (const float4*)(g_k + (size_t)bh * SEQ * HW);
    const float4* V4 = (const float4*)(g_v + (size_t)bh * SEQ * HW);

    const int tid  = threadIdx.x;
    const int warp = tid >> 5;
    const int lane = tid & 31;
    const int r0   = warp * 8;

    const float slope = exp2f(-0.5f * (float)(h + 1));  // ALiBi slope for head h

    // Load full Q tile: 64 rows x 16 float4 = 1024 float4s, 256 threads -> 4 each.
#pragma unroll
    for (int i = tid; i < 64 * 16; i += 256) {
        int r = i >> 4, cg = i & 15;
        ((float4*)Qs)[r * 16 + cg] = Q4[(size_t)(q0 + r) * 16 + cg];
    }

    float m_i[8], l_i[8], o0[8], o1[8];
#pragma unroll
    for (int r = 0; r < 8; r++) { m_i[r] = -1e30f; l_i[r] = 0.f; o0[r] = 0.f; o1[r] = 0.f; }

    for (int kt = 0; kt <= qt; kt++) {
        const int k0g = kt * 64;
        __syncthreads();   // Q visible (first iter); prior-iter Vs reads done
#pragma unroll
        for (int i = tid; i < 64 * 16; i += 256) {
            int r = i >> 4, cg = i & 15;
            ((float4*)Ks)[r * 17 + cg] = K4[(size_t)(k0g + r) * 16 + cg];
            ((float4*)Vs)[r * 17 + cg] = V4[(size_t)(k0g + r) * 16 + cg];
        }
        __syncthreads();

        // --- S = Q K^T ---
        float s0[8], s1[8];
#pragma unroll
        for (int r = 0; r < 8; r++) { s0[r] = 0.f; s1[r] = 0.f; }

        const float4* Ks4 = (const float4*)Ks;
        const float4* Qs4 = (const float4*)Qs;
#pragma unroll
        for (int i = 0; i < 16; i++) {
            float4 ka = Ks4[lane * 17 + i];          // lane-strided, conflict-free (pad 68)
            float4 kb = Ks4[(lane + 32) * 17 + i];
#pragma unroll
            for (int r = 0; r < 8; r++) {
                float4 qv = Qs4[(r0 + r) * 16 + i];  // broadcast
                s0[r] += qv.x*ka.x + qv.y*ka.y + qv.z*ka.z + qv.w*ka.w;
                s1[r] += qv.x*kb.x + qv.y*kb.y + qv.z*kb.z + qv.w*kb.w;
            }
        }

        // --- scale + ALiBi + causal mask + online softmax ---
        const bool diag = (kt == qt);
#pragma unroll
        for (int r = 0; r < 8; r++) {
            int row  = q0 + r0 + r;
            int col0 = k0g + lane;
            int col1 = k0g + lane + 32;
            float v0 = s0[r] * SM_SCALE + slope * (float)(col0 - row);
            float v1 = s1[r] * SM_SCALE + slope * (float)(col1 - row);
            if (diag) {
                if (col0 > row) v0 -= 1e9f;
                if (col1 > row) v1 -= 1e9f;
            }
            float tm = fmaxf(v0, v1);
#pragma unroll
            for (int off = 16; off > 0; off >>= 1)
                tm = fmaxf(tm, __shfl_xor_sync(0xffffffffu, tm, off));
            float mn   = fmaxf(m_i[r], tm);
            float corr = __expf(m_i[r] - mn);
            float p0   = __expf(v0 - mn);
            float p1   = __expf(v1 - mn);
            float rs   = p0 + p1;
#pragma unroll
            for (int off = 16; off > 0; off >>= 1)
                rs += __shfl_xor_sync(0xffffffffu, rs, off);
            l_i[r] = l_i[r] * corr + rs;
            o0[r] *= corr;
            o1[r] *= corr;
            m_i[r] = mn;
            Ps[(r0 + r) * 68 + lane]      = p0;
            Ps[(r0 + r) * 68 + lane + 32] = p1;
        }
        __syncwarp();   // Ps rows are private to this warp

        // --- O += P V ---
        const float4* Ps4 = (const float4*)Ps;
#pragma unroll
        for (int cb = 0; cb < 16; cb++) {
            int cbase = cb * 4;
            float v00 = Vs[(cbase+0)*68 + lane];
            float v01 = Vs[(cbase+1)*68 + lane];
            float v02 = Vs[(cbase+2)*68 + lane];
            float v03 = Vs[(cbase+3)*68 + lane];
            float v10 = Vs[(cbase+0)*68 + lane + 32];
            float v11 = Vs[(cbase+1)*68 + lane + 32];
            float v12 = Vs[(cbase+2)*68 + lane + 32];
            float v13 = Vs[(cbase+3)*68 + lane + 32];
#pragma unroll
            for (int r = 0; r < 8; r++) {
                float4 p = Ps4[(r0 + r) * 17 + cb];  // broadcast
                o0[r] += p.x*v00 + p.y*v01 + p.z*v02 + p.w*v03;
                o1[r] += p.x*v10 + p.y*v11 + p.z*v12 + p.w*v13;
            }
        }
    }

    // Final normalize + store to [B, S, D].
    float* outp = out + (size_t)b * SEQ * DM + (size_t)h * HW;
#pragma unroll
    for (int r = 0; r < 8; r++) {
        int row = q0 + r0 + r;
        float inv = 1.0f / l_i[r];
        outp[(size_t)row * DM + lane]      = o0[r] * inv;
        outp[(size_t)row * DM + lane + 32] = o1[r] * inv;
    }
}

// ---------------------------------------------------------------------------
// Launch: inputs order = queries, keys, values, mask, Wq, Wk, Wv.
// ---------------------------------------------------------------------------
extern "C" void kernel_launch(void* const* d_in, const int* in_sizes, int n_in,
                              void* d_out, int out_size)
{
    (void)in_sizes; (void)n_in; (void)out_size;
    const float* q  = (const float*)d_in[0];
    const float* k  = (const float*)d_in[1];
    const float* v  = (const float*)d_in[2];
    const float* wq = (const float*)d_in[4];
    const float* wk = (const float*)d_in[5];
    const float* wv = (const float*)d_in[6];
    float* out = (float*)d_out;

    const int attn_smem = (4096 + 3 * 4352) * (int)sizeof(float);  // 68608 B
    cudaFuncSetAttribute(attn_kernel, cudaFuncAttributeMaxDynamicSharedMemorySize, attn_smem);

    proj_kernel<<<dim3(DM/64, (BATCH*SEQ)/64, 3), 256>>>(q, k, v, wq, wk, wv);
    attn_kernel<<<dim3(SEQ/64, BATCH*NH), 256, attn_smem>>>(out);
}

// round 4
// speedup vs baseline: 1.4732x; 1.4732x over previous
#include <cuda_runtime.h>
#include <cuda_bf16.h>
#include <cstdint>
#include <math.h>

#define BATCH 2
#define SEQ   2048
#define DM    1024
#define NH    16
#define HW    64
#define SM_SCALE 0.125f   // 1/sqrt(64)

// Scratch for projected Q/K/V in [B, H, S, hw] layout (16 MB each).
__device__ float g_q[BATCH*NH*SEQ*HW];
__device__ float g_k[BATCH*NH*SEQ*HW];
__device__ float g_v[BATCH*NH*SEQ*HW];

// ---------------------------------------------------------------------------
// Helpers
// ---------------------------------------------------------------------------
__device__ __forceinline__ uint32_t smem_u32(const void* p) {
    uint32_t a;
    asm("{ .reg .u64 t; cvta.to.shared.u64 t, %1; cvt.u32.u64 %0, t; }"
        : "=r"(a) : "l"(p));
    return a;
}

__device__ __forceinline__ void ldm4(uint32_t r[4], uint32_t addr) {
    asm volatile("ldmatrix.sync.aligned.m8n8.x4.shared.b16 {%0,%1,%2,%3}, [%4];"
                 : "=r"(r[0]), "=r"(r[1]), "=r"(r[2]), "=r"(r[3]) : "r"(addr));
}

__device__ __forceinline__ void mma_bf16(float acc[4], const uint32_t a[4],
                                         uint32_t b0, uint32_t b1) {
    asm volatile(
        "mma.sync.aligned.m16n8k16.row.col.f32.bf16.bf16.f32 "
        "{%0,%1,%2,%3}, {%4,%5,%6,%7}, {%8,%9}, {%0,%1,%2,%3};"
        : "+f"(acc[0]), "+f"(acc[1]), "+f"(acc[2]), "+f"(acc[3])
        : "r"(a[0]), "r"(a[1]), "r"(a[2]), "r"(a[3]), "r"(b0), "r"(b1));
}

// Split a into bf16 hi + residual; return packed hi pair, output residuals.
__device__ __forceinline__ uint32_t packhi(float a, float b, float& ra, float& rb) {
    __nv_bfloat16 ha = __float2bfloat16(a);
    __nv_bfloat16 hb = __float2bfloat16(b);
    ra = a - __bfloat162float(ha);
    rb = b - __bfloat162float(hb);
    return (uint32_t)__bfloat16_as_ushort(ha) |
           ((uint32_t)__bfloat16_as_ushort(hb) << 16);
}
__device__ __forceinline__ uint32_t packlo(float a, float b) {
    return (uint32_t)__bfloat16_as_ushort(__float2bfloat16(a)) |
           ((uint32_t)__bfloat16_as_ushort(__float2bfloat16(b)) << 16);
}

// ---------------------------------------------------------------------------
// Projection GEMM on mma.sync bf16 (HMMA): C[m,n] = sum_k X[m,k] * W[n,k].
// CTA 128x128, BK=32, 8 warps (4M x 2N), warp tile 32x64.
// bf16 hi/lo split, 3 accumulated passes -> ~1e-5 accuracy.
// smem rows padded to 40 bf16 (80B) -> ldmatrix conflict-free.
// grid = (8, 32, 3), block = 256.
// ---------------------------------------------------------------------------
#define SROW 40

__global__ __launch_bounds__(256) void proj_mma(
    const float* __restrict__ xq, const float* __restrict__ xk, const float* __restrict__ xv,
    const float* __restrict__ wq, const float* __restrict__ wk, const float* __restrict__ wv)
{
    __shared__ __align__(16) unsigned short sAh[128*SROW];
    __shared__ __align__(16) unsigned short sAl[128*SROW];
    __shared__ __align__(16) unsigned short sBh[128*SROW];
    __shared__ __align__(16) unsigned short sBl[128*SROW];

    const int z = blockIdx.z;
    const float* X = (z == 0) ? xq : (z == 1) ? xk : xv;
    const float* W = (z == 0) ? wq : (z == 1) ? wk : wv;
    float*       O = (z == 0) ? g_q : (z == 1) ? g_k : g_v;

    const int tid   = threadIdx.x;
    const int wid   = tid >> 5;
    const int lane  = tid & 31;
    const int warpM = wid >> 1;      // 0..3
    const int warpN = wid & 1;       // 0..1
    const int m0    = blockIdx.y * 128;
    const int n0    = blockIdx.x * 128;

    const float4* X4 = (const float4*)X;
    const float4* W4 = (const float4*)W;

    // Per-thread ldmatrix base addresses (bytes).
    const uint32_t sAh32 = smem_u32(sAh), sAl32 = smem_u32(sAl);
    const uint32_t sBh32 = smem_u32(sBh), sBl32 = smem_u32(sBl);
    const uint32_t aRow = (uint32_t)(warpM * 32 + (lane & 15));
    const uint32_t aCol = (uint32_t)((lane >> 4) << 3);          // +8 bf16 for upper half
    const uint32_t aOff = (aRow * SROW + aCol) * 2;
    const uint32_t bRow = (uint32_t)(warpN * 64 + (lane & 7) + ((lane >> 4) << 3));
    const uint32_t bCol = (uint32_t)(((lane >> 3) & 1) << 3);
    const uint32_t bOff = (bRow * SROW + bCol) * 2;

    float acc[2][8][4];
#pragma unroll
    for (int mf = 0; mf < 2; mf++)
#pragma unroll
        for (int nf = 0; nf < 8; nf++)
#pragma unroll
            for (int i = 0; i < 4; i++) acc[mf][nf][i] = 0.0f;

    const int row = tid >> 3;        // 0..31 step, +32 per t
    const int cg  = tid & 7;

    float4 pa[4], pb[4];
#pragma unroll
    for (int t = 0; t < 4; t++) {
        int r = row + t * 32;
        pa[t] = X4[(size_t)(m0 + r) * 256 + cg];
        pb[t] = W4[(size_t)(n0 + r) * 256 + cg];
    }

    for (int c = 0; c < 32; c++) {
        if (c) __syncthreads();      // prior chunk's ldmatrix reads done

        // Split + store staged chunk to smem.
#pragma unroll
        for (int t = 0; t < 4; t++) {
            int r   = row + t * 32;
            int idx = r * SROW + cg * 4;
            float r0, r1, r2, r3;
            uint32_t h01 = packhi(pa[t].x, pa[t].y, r0, r1);
            uint32_t h23 = packhi(pa[t].z, pa[t].w, r2, r3);
            *(uint2*)(sAh + idx) = make_uint2(h01, h23);
            *(uint2*)(sAl + idx) = make_uint2(packlo(r0, r1), packlo(r2, r3));
            h01 = packhi(pb[t].x, pb[t].y, r0, r1);
            h23 = packhi(pb[t].z, pb[t].w, r2, r3);
            *(uint2*)(sBh + idx) = make_uint2(h01, h23);
            *(uint2*)(sBl + idx) = make_uint2(packlo(r0, r1), packlo(r2, r3));
        }
        __syncthreads();

        // Prefetch next chunk while computing this one.
        if (c < 31) {
#pragma unroll
            for (int t = 0; t < 4; t++) {
                int r = row + t * 32;
                pa[t] = X4[(size_t)(m0 + r) * 256 + (c + 1) * 8 + cg];
                pb[t] = W4[(size_t)(n0 + r) * 256 + (c + 1) * 8 + cg];
            }
        }

        // Compute: 2 k16 steps.
#pragma unroll
        for (int ks = 0; ks < 2; ks++) {
            const uint32_t kByte = (uint32_t)(ks * 32);   // 16 bf16 = 32B
            uint32_t ah[2][4], al[2][4], bh[4][4], bl[4][4];
#pragma unroll
            for (int mf = 0; mf < 2; mf++) {
                uint32_t ad = aOff + (uint32_t)(mf * 16 * SROW * 2) + kByte;
                ldm4(ah[mf], sAh32 + ad);
                ldm4(al[mf], sAl32 + ad);
            }
#pragma unroll
            for (int p = 0; p < 4; p++) {
                uint32_t bd = bOff + (uint32_t)(p * 16 * SROW * 2) + kByte;
                ldm4(bh[p], sBh32 + bd);
                ldm4(bl[p], sBl32 + bd);
            }
#pragma unroll
            for (int mf = 0; mf < 2; mf++)
#pragma unroll
                for (int nf = 0; nf < 8; nf++) {
                    const int p = nf >> 1, q = (nf & 1) * 2;
                    mma_bf16(acc[mf][nf], ah[mf], bh[p][q], bh[p][q+1]);  // Ah*Bh
                    mma_bf16(acc[mf][nf], al[mf], bh[p][q], bh[p][q+1]);  // Al*Bh
                    mma_bf16(acc[mf][nf], ah[mf], bl[p][q], bl[p][q+1]);  // Ah*Bl
                }
        }
    }

    // Epilogue: write into [B, H, S, hw] layout. A warp's 64 n-cols = 1 head.
    const int g  = lane >> 2;
    const int t2 = (lane & 3) << 1;
#pragma unroll
    for (int mf = 0; mf < 2; mf++) {
        int mA  = m0 + warpM * 32 + mf * 16 + g;
        int mB  = mA + 8;
        int bbA = mA >> 11, ssA = mA & (SEQ - 1);
        int bbB = mB >> 11, ssB = mB & (SEQ - 1);
#pragma unroll
        for (int nf = 0; nf < 8; nf++) {
            int n  = n0 + warpN * 64 + nf * 8 + t2;
            int hh = n >> 6, dd = n & 63;
            float* pA = O + (((size_t)(bbA * NH + hh)) * SEQ + ssA) * HW + dd;
            float* pB = O + (((size_t)(bbB * NH + hh)) * SEQ + ssB) * HW + dd;
            *(float2*)pA = make_float2(acc[mf][nf][0], acc[mf][nf][1]);
            *(float2*)pB = make_float2(acc[mf][nf][2], acc[mf][nf][3]);
        }
    }
}

// ---------------------------------------------------------------------------
// Flash attention with causal mask + ALiBi (unchanged from passing R2 kernel).
// ---------------------------------------------------------------------------
__global__ __launch_bounds__(256) void attn_kernel(float* __restrict__ out)
{
    extern __shared__ float fsm[];
    float* Qs = fsm;                  // 4096 floats
    float* Ks = fsm + 4096;           // 4352 floats (64 x 68)
    float* Vs = Ks + 4352;
    float* Ps = Vs + 4352;

    const int bh = blockIdx.y;
    const int b  = bh >> 4;
    const int h  = bh & 15;
    const int qt = blockIdx.x;
    const int q0 = qt * 64;

    const float4* Q4 = (const float4*)(g_q + (size_t)bh * SEQ * HW);
    const float4* K4 = (const float4*)(g_k + (size_t)bh * SEQ * HW);
    const float4* V4 = (const float4*)(g_v + (size_t)bh * SEQ * HW);

    const int tid  = threadIdx.x;
    const int warp = tid >> 5;
    const int lane = tid & 31;
    const int r0   = warp * 8;

    const float slope = exp2f(-0.5f * (float)(h + 1));

#pragma unroll
    for (int i = tid; i < 64 * 16; i += 256) {
        int r = i >> 4, cg = i & 15;
        ((float4*)Qs)[r * 16 + cg] = Q4[(size_t)(q0 + r) * 16 + cg];
    }

    float m_i[8], l_i[8], o0[8], o1[8];
#pragma unroll
    for (int r = 0; r < 8; r++) { m_i[r] = -1e30f; l_i[r] = 0.f; o0[r] = 0.f; o1[r] = 0.f; }

    for (int kt = 0; kt <= qt; kt++) {
        const int k0g = kt * 64;
        __syncthreads();
#pragma unroll
        for (int i = tid; i < 64 * 16; i += 256) {
            int r = i >> 4, cg = i & 15;
            ((float4*)Ks)[r * 17 + cg] = K4[(size_t)(k0g + r) * 16 + cg];
            ((float4*)Vs)[r * 17 + cg] = V4[(size_t)(k0g + r) * 16 + cg];
        }
        __syncthreads();

        float s0[8], s1[8];
#pragma unroll
        for (int r = 0; r < 8; r++) { s0[r] = 0.f; s1[r] = 0.f; }

        const float4* Ks4 = (const float4*)Ks;
        const float4* Qs4 = (const float4*)Qs;
#pragma unroll
        for (int i = 0; i < 16; i++) {
            float4 ka = Ks4[lane * 17 + i];
            float4 kb = Ks4[(lane + 32) * 17 + i];
#pragma unroll
            for (int r = 0; r < 8; r++) {
                float4 qv = Qs4[(r0 + r) * 16 + i];
                s0[r] += qv.x*ka.x + qv.y*ka.y + qv.z*ka.z + qv.w*ka.w;
                s1[r] += qv.x*kb.x + qv.y*kb.y + qv.z*kb.z + qv.w*kb.w;
            }
        }

        const bool diag = (kt == qt);
#pragma unroll
        for (int r = 0; r < 8; r++) {
            int row  = q0 + r0 + r;
            int col0 = k0g + lane;
            int col1 = k0g + lane + 32;
            float v0 = s0[r] * SM_SCALE + slope * (float)(col0 - row);
            float v1 = s1[r] * SM_SCALE + slope * (float)(col1 - row);
            if (diag) {
                if (col0 > row) v0 -= 1e9f;
                if (col1 > row) v1 -= 1e9f;
            }
            float tm = fmaxf(v0, v1);
#pragma unroll
            for (int off = 16; off > 0; off >>= 1)
                tm = fmaxf(tm, __shfl_xor_sync(0xffffffffu, tm, off));
            float mn   = fmaxf(m_i[r], tm);
            float corr = __expf(m_i[r] - mn);
            float p0   = __expf(v0 - mn);
            float p1   = __expf(v1 - mn);
            float rs   = p0 + p1;
#pragma unroll
            for (int off = 16; off > 0; off >>= 1)
                rs += __shfl_xor_sync(0xffffffffu, rs, off);
            l_i[r] = l_i[r] * corr + rs;
            o0[r] *= corr;
            o1[r] *= corr;
            m_i[r] = mn;
            Ps[(r0 + r) * 68 + lane]      = p0;
            Ps[(r0 + r) * 68 + lane + 32] = p1;
        }
        __syncwarp();

        const float4* Ps4 = (const float4*)Ps;
#pragma unroll
        for (int cb = 0; cb < 16; cb++) {
            int cbase = cb * 4;
            float v00 = Vs[(cbase+0)*68 + lane];
            float v01 = Vs[(cbase+1)*68 + lane];
            float v02 = Vs[(cbase+2)*68 + lane];
            float v03 = Vs[(cbase+3)*68 + lane];
            float v10 = Vs[(cbase+0)*68 + lane + 32];
            float v11 = Vs[(cbase+1)*68 + lane + 32];
            float v12 = Vs[(cbase+2)*68 + lane + 32];
            float v13 = Vs[(cbase+3)*68 + lane + 32];
#pragma unroll
            for (int r = 0; r < 8; r++) {
                float4 p = Ps4[(r0 + r) * 17 + cb];
                o0[r] += p.x*v00 + p.y*v01 + p.z*v02 + p.w*v03;
                o1[r] += p.x*v10 + p.y*v11 + p.z*v12 + p.w*v13;
            }
        }
    }

    float* outp = out + (size_t)b * SEQ * DM + (size_t)h * HW;
#pragma unroll
    for (int r = 0; r < 8; r++) {
        int row = q0 + r0 + r;
        float inv = 1.0f / l_i[r];
        outp[(size_t)row * DM + lane]      = o0[r] * inv;
        outp[(size_t)row * DM + lane + 32] = o1[r] * inv;
    }
}

// ---------------------------------------------------------------------------
// Launch: inputs order = queries, keys, values, mask, Wq, Wk, Wv.
// ---------------------------------------------------------------------------
extern "C" void kernel_launch(void* const* d_in, const int* in_sizes, int n_in,
                              void* d_out, int out_size)
{
    (void)in_sizes; (void)n_in; (void)out_size;
    const float* q  = (const float*)d_in[0];
    const float* k  = (const float*)d_in[1];
    const float* v  = (const float*)d_in[2];
    const float* wq = (const float*)d_in[4];
    const float* wk = (const float*)d_in[5];
    const float* wv = (const float*)d_in[6];
    float* out = (float*)d_out;

    const int attn_smem = (4096 + 3 * 4352) * (int)sizeof(float);  // 68608 B
    cudaFuncSetAttribute(attn_kernel, cudaFuncAttributeMaxDynamicSharedMemorySize, attn_smem);

    proj_mma<<<dim3(DM/128, (BATCH*SEQ)/128, 3), 256>>>(q, k, v, wq, wk, wv);
    attn_kernel<<<dim3(SEQ/64, BATCH*NH), 256, attn_smem>>>(out);
}

// round 5
// speedup vs baseline: 1.7122x; 1.1623x over previous
#include <cuda_runtime.h>
#include <cuda_bf16.h>
#include <cstdint>
#include <math.h>

#define BATCH 2
#define SEQ   2048
#define DM    1024
#define NH    16
#define HW    64
#define SM_SCALE 0.125f   // 1/sqrt(64)

// Scratch for projected Q/K/V in [B, H, S, hw] layout (16 MB each).
__device__ float g_q[BATCH*NH*SEQ*HW];
__device__ float g_k[BATCH*NH*SEQ*HW];
__device__ float g_v[BATCH*NH*SEQ*HW];

// ---------------------------------------------------------------------------
// Helpers
// ---------------------------------------------------------------------------
__device__ __forceinline__ uint32_t smem_u32(const void* p) {
    uint32_t a;
    asm("{ .reg .u64 t; cvta.to.shared.u64 t, %1; cvt.u32.u64 %0, t; }"
        : "=r"(a) : "l"(p));
    return a;
}

__device__ __forceinline__ void ldm4(uint32_t r[4], uint32_t addr) {
    asm volatile("ldmatrix.sync.aligned.m8n8.x4.shared.b16 {%0,%1,%2,%3}, [%4];"
                 : "=r"(r[0]), "=r"(r[1]), "=r"(r[2]), "=r"(r[3]) : "r"(addr));
}
__device__ __forceinline__ void ldm4t(uint32_t r[4], uint32_t addr) {
    asm volatile("ldmatrix.sync.aligned.m8n8.x4.trans.shared.b16 {%0,%1,%2,%3}, [%4];"
                 : "=r"(r[0]), "=r"(r[1]), "=r"(r[2]), "=r"(r[3]) : "r"(addr));
}

__device__ __forceinline__ void mma_bf16(float acc[4], const uint32_t a[4],
                                         uint32_t b0, uint32_t b1) {
    asm volatile(
        "mma.sync.aligned.m16n8k16.row.col.f32.bf16.bf16.f32 "
        "{%0,%1,%2,%3}, {%4,%5,%6,%7}, {%8,%9}, {%0,%1,%2,%3};"
        : "+f"(acc[0]), "+f"(acc[1]), "+f"(acc[2]), "+f"(acc[3])
        : "r"(a[0]), "r"(a[1]), "r"(a[2]), "r"(a[3]), "r"(b0), "r"(b1));
}

// Split a into bf16 hi + residual; return packed hi pair, output residuals.
__device__ __forceinline__ uint32_t packhi(float a, float b, float& ra, float& rb) {
    __nv_bfloat16 ha = __float2bfloat16(a);
    __nv_bfloat16 hb = __float2bfloat16(b);
    ra = a - __bfloat162float(ha);
    rb = b - __bfloat162float(hb);
    return (uint32_t)__bfloat16_as_ushort(ha) |
           ((uint32_t)__bfloat16_as_ushort(hb) << 16);
}
__device__ __forceinline__ uint32_t packlo(float a, float b) {
    return (uint32_t)__bfloat16_as_ushort(__float2bfloat16(a)) |
           ((uint32_t)__bfloat16_as_ushort(__float2bfloat16(b)) << 16);
}

// ---------------------------------------------------------------------------
// Projection GEMM on mma.sync bf16 (unchanged from R4 passing kernel).
// ---------------------------------------------------------------------------
#define SROW 40

__global__ __launch_bounds__(256) void proj_mma(
    const float* __restrict__ xq, const float* __restrict__ xk, const float* __restrict__ xv,
    const float* __restrict__ wq, const float* __restrict__ wk, const float* __restrict__ wv)
{
    __shared__ __align__(16) unsigned short sAh[128*SROW];
    __shared__ __align__(16) unsigned short sAl[128*SROW];
    __shared__ __align__(16) unsigned short sBh[128*SROW];
    __shared__ __align__(16) unsigned short sBl[128*SROW];

    const int z = blockIdx.z;
    const float* X = (z == 0) ? xq : (z == 1) ? xk : xv;
    const float* W = (z == 0) ? wq : (z == 1) ? wk : wv;
    float*       O = (z == 0) ? g_q : (z == 1) ? g_k : g_v;

    const int tid   = threadIdx.x;
    const int wid   = tid >> 5;
    const int lane  = tid & 31;
    const int warpM = wid >> 1;
    const int warpN = wid & 1;
    const int m0    = blockIdx.y * 128;
    const int n0    = blockIdx.x * 128;

    const float4* X4 = (const float4*)X;
    const float4* W4 = (const float4*)W;

    const uint32_t sAh32 = smem_u32(sAh), sAl32 = smem_u32(sAl);
    const uint32_t sBh32 = smem_u32(sBh), sBl32 = smem_u32(sBl);
    const uint32_t aRow = (uint32_t)(warpM * 32 + (lane & 15));
    const uint32_t aCol = (uint32_t)((lane >> 4) << 3);
    const uint32_t aOff = (aRow * SROW + aCol) * 2;
    const uint32_t bRow = (uint32_t)(warpN * 64 + (lane & 7) + ((lane >> 4) << 3));
    const uint32_t bCol = (uint32_t)(((lane >> 3) & 1) << 3);
    const uint32_t bOff = (bRow * SROW + bCol) * 2;

    float acc[2][8][4];
#pragma unroll
    for (int mf = 0; mf < 2; mf++)
#pragma unroll
        for (int nf = 0; nf < 8; nf++)
#pragma unroll
            for (int i = 0; i < 4; i++) acc[mf][nf][i] = 0.0f;

    const int row = tid >> 3;
    const int cg  = tid & 7;

    float4 pa[4], pb[4];
#pragma unroll
    for (int t = 0; t < 4; t++) {
        int r = row + t * 32;
        pa[t] = X4[(size_t)(m0 + r) * 256 + cg];
        pb[t] = W4[(size_t)(n0 + r) * 256 + cg];
    }

    for (int c = 0; c < 32; c++) {
        if (c) __syncthreads();

#pragma unroll
        for (int t = 0; t < 4; t++) {
            int r   = row + t * 32;
            int idx = r * SROW + cg * 4;
            float r0, r1, r2, r3;
            uint32_t h01 = packhi(pa[t].x, pa[t].y, r0, r1);
            uint32_t h23 = packhi(pa[t].z, pa[t].w, r2, r3);
            *(uint2*)(sAh + idx) = make_uint2(h01, h23);
            *(uint2*)(sAl + idx) = make_uint2(packlo(r0, r1), packlo(r2, r3));
            h01 = packhi(pb[t].x, pb[t].y, r0, r1);
            h23 = packhi(pb[t].z, pb[t].w, r2, r3);
            *(uint2*)(sBh + idx) = make_uint2(h01, h23);
            *(uint2*)(sBl + idx) = make_uint2(packlo(r0, r1), packlo(r2, r3));
        }
        __syncthreads();

        if (c < 31) {
#pragma unroll
            for (int t = 0; t < 4; t++) {
                int r = row + t * 32;
                pa[t] = X4[(size_t)(m0 + r) * 256 + (c + 1) * 8 + cg];
                pb[t] = W4[(size_t)(n0 + r) * 256 + (c + 1) * 8 + cg];
            }
        }

#pragma unroll
        for (int ks = 0; ks < 2; ks++) {
            const uint32_t kByte = (uint32_t)(ks * 32);
            uint32_t ah[2][4], al[2][4], bh[4][4], bl[4][4];
#pragma unroll
            for (int mf = 0; mf < 2; mf++) {
                uint32_t ad = aOff + (uint32_t)(mf * 16 * SROW * 2) + kByte;
                ldm4(ah[mf], sAh32 + ad);
                ldm4(al[mf], sAl32 + ad);
            }
#pragma unroll
            for (int p = 0; p < 4; p++) {
                uint32_t bd = bOff + (uint32_t)(p * 16 * SROW * 2) + kByte;
                ldm4(bh[p], sBh32 + bd);
                ldm4(bl[p], sBl32 + bd);
            }
#pragma unroll
            for (int mf = 0; mf < 2; mf++)
#pragma unroll
                for (int nf = 0; nf < 8; nf++) {
                    const int p = nf >> 1, q = (nf & 1) * 2;
                    mma_bf16(acc[mf][nf], ah[mf], bh[p][q], bh[p][q+1]);
                    mma_bf16(acc[mf][nf], al[mf], bh[p][q], bh[p][q+1]);
                    mma_bf16(acc[mf][nf], ah[mf], bl[p][q], bl[p][q+1]);
                }
        }
    }

    const int g  = lane >> 2;
    const int t2 = (lane & 3) << 1;
#pragma unroll
    for (int mf = 0; mf < 2; mf++) {
        int mA  = m0 + warpM * 32 + mf * 16 + g;
        int mB  = mA + 8;
        int bbA = mA >> 11, ssA = mA & (SEQ - 1);
        int bbB = mB >> 11, ssB = mB & (SEQ - 1);
#pragma unroll
        for (int nf = 0; nf < 8; nf++) {
            int n  = n0 + warpN * 64 + nf * 8 + t2;
            int hh = n >> 6, dd = n & 63;
            float* pA = O + (((size_t)(bbA * NH + hh)) * SEQ + ssA) * HW + dd;
            float* pB = O + (((size_t)(bbB * NH + hh)) * SEQ + ssB) * HW + dd;
            *(float2*)pA = make_float2(acc[mf][nf][0], acc[mf][nf][1]);
            *(float2*)pB = make_float2(acc[mf][nf][2], acc[mf][nf][3]);
        }
    }
}

// ---------------------------------------------------------------------------
// Flash attention on mma.sync bf16 (hi/lo 3-pass), causal + ALiBi.
// Block = 128 q-rows, 8 warps; warp w owns q-rows [16w,16w+16) fully.
// smem tiles padded to 72 bf16/row (144B stride -> ldmatrix conflict-free).
// grid = (S/128=16, B*H=32), block = 256. Dynamic smem 110592 B.
// ---------------------------------------------------------------------------
#define AROW 72
#define ATILE (128*AROW)   // bf16 elements per tile

__global__ __launch_bounds__(256, 1) void attn_mma(float* __restrict__ out)
{
    extern __shared__ unsigned short asm_[];
    unsigned short* sQh = asm_;
    unsigned short* sQl = asm_ + ATILE;
    unsigned short* sKh = asm_ + 2*ATILE;
    unsigned short* sKl = asm_ + 3*ATILE;
    unsigned short* sVh = asm_ + 4*ATILE;
    unsigned short* sVl = asm_ + 5*ATILE;

    const uint32_t qh32 = smem_u32(sQh), ql32 = smem_u32(sQl);
    const uint32_t kh32 = smem_u32(sKh), kl32 = smem_u32(sKl);
    const uint32_t vh32 = smem_u32(sVh), vl32 = smem_u32(sVl);

    const int bh = blockIdx.y;
    const int b  = bh >> 4;
    const int h  = bh & 15;
    const int qt = (int)gridDim.x - 1 - (int)blockIdx.x;  // heavy tiles first
    const int q0 = qt * 128;

    const int tid  = threadIdx.x;
    const int warp = tid >> 5;
    const int lane = tid & 31;
    const int g    = lane >> 2;
    const int t2   = (lane & 3) << 1;

    const float slope = exp2f(-0.5f * (float)(h + 1));

    const float4* Qg = (const float4*)(g_q + (size_t)bh * SEQ * HW);
    const float4* Kg = (const float4*)(g_k + (size_t)bh * SEQ * HW);
    const float4* Vg = (const float4*)(g_v + (size_t)bh * SEQ * HW);

    // ---- load Q tile (hi/lo split) ----
#pragma unroll
    for (int t = 0; t < 8; t++) {
        int i = tid + t * 256;        // 0..2047
        int r = i >> 4, c4 = i & 15;
        float4 qv = Qg[(size_t)(q0 + r) * 16 + c4];
        int idx = r * AROW + c4 * 4;
        float r0, r1, r2, r3;
        uint32_t h01 = packhi(qv.x, qv.y, r0, r1);
        uint32_t h23 = packhi(qv.z, qv.w, r2, r3);
        *(uint2*)(sQh + idx) = make_uint2(h01, h23);
        *(uint2*)(sQl + idx) = make_uint2(packlo(r0, r1), packlo(r2, r3));
    }

    // ldmatrix element offsets
    const uint32_t aElem = (uint32_t)((warp * 16 + (lane & 15)) * AROW + ((lane >> 4) << 3));
    const uint32_t bElem = (uint32_t)(((lane & 7) + ((lane >> 4) << 3)) * AROW + (((lane >> 3) & 1) << 3));
    const uint32_t vElem = (uint32_t)((lane & 15) * AROW + ((lane >> 4) << 3));

    float oacc[8][4];
#pragma unroll
    for (int nf = 0; nf < 8; nf++)
#pragma unroll
        for (int e = 0; e < 4; e++) oacc[nf][e] = 0.0f;

    float m0r = -3e38f, m1r = -3e38f, l0 = 0.0f, l1 = 0.0f;
    const int row0 = q0 + warp * 16 + g;
    const int row1 = row0 + 8;

    for (int kt = 0; kt <= qt; kt++) {
        const int k0g = kt * 128;
        __syncthreads();
        // ---- load K,V tiles (hi/lo) ----
#pragma unroll
        for (int t = 0; t < 8; t++) {
            int i = tid + t * 256;
            int r = i >> 4, c4 = i & 15;
            int idx = r * AROW + c4 * 4;
            float4 kv = Kg[(size_t)(k0g + r) * 16 + c4];
            float r0, r1, r2, r3;
            uint32_t h01 = packhi(kv.x, kv.y, r0, r1);
            uint32_t h23 = packhi(kv.z, kv.w, r2, r3);
            *(uint2*)(sKh + idx) = make_uint2(h01, h23);
            *(uint2*)(sKl + idx) = make_uint2(packlo(r0, r1), packlo(r2, r3));
            float4 vv = Vg[(size_t)(k0g + r) * 16 + c4];
            h01 = packhi(vv.x, vv.y, r0, r1);
            h23 = packhi(vv.z, vv.w, r2, r3);
            *(uint2*)(sVh + idx) = make_uint2(h01, h23);
            *(uint2*)(sVl + idx) = make_uint2(packlo(r0, r1), packlo(r2, r3));
        }
        __syncthreads();

        // ---- S = Q K^T (3-pass hi/lo) ----
        float sacc[16][4];
#pragma unroll
        for (int nf = 0; nf < 16; nf++)
#pragma unroll
            for (int e = 0; e < 4; e++) sacc[nf][e] = 0.0f;

#pragma unroll
        for (int ks = 0; ks < 4; ks++) {
            uint32_t ah[4], al[4];
            ldm4(ah, qh32 + (aElem + ks * 16) * 2);
            ldm4(al, ql32 + (aElem + ks * 16) * 2);
#pragma unroll
            for (int p = 0; p < 8; p++) {
                uint32_t bhx[4], blx[4];
                uint32_t bd = (bElem + (uint32_t)(p * 16 * AROW) + (uint32_t)(ks * 16)) * 2;
                ldm4(bhx, kh32 + bd);
                ldm4(blx, kl32 + bd);
                mma_bf16(sacc[2*p],   ah, bhx[0], bhx[1]);
                mma_bf16(sacc[2*p],   al, bhx[0], bhx[1]);
                mma_bf16(sacc[2*p],   ah, blx[0], blx[1]);
                mma_bf16(sacc[2*p+1], ah, bhx[2], bhx[3]);
                mma_bf16(sacc[2*p+1], al, bhx[2], bhx[3]);
                mma_bf16(sacc[2*p+1], ah, blx[2], blx[3]);
            }
        }

        // ---- scale + ALiBi + causal mask; row max ----
        const bool diag = (kt == qt);
        float mx0 = -3e38f, mx1 = -3e38f;
#pragma unroll
        for (int nf = 0; nf < 16; nf++) {
            int c0 = k0g + nf * 8 + t2;
            int c1 = c0 + 1;
            float v0 = sacc[nf][0] * SM_SCALE + slope * (float)(c0 - row0);
            float v1 = sacc[nf][1] * SM_SCALE + slope * (float)(c1 - row0);
            float v2 = sacc[nf][2] * SM_SCALE + slope * (float)(c0 - row1);
            float v3 = sacc[nf][3] * SM_SCALE + slope * (float)(c1 - row1);
            if (diag) {
                if (c0 > row0) v0 = -3e38f;
                if (c1 > row0) v1 = -3e38f;
                if (c0 > row1) v2 = -3e38f;
                if (c1 > row1) v3 = -3e38f;
            }
            sacc[nf][0] = v0; sacc[nf][1] = v1; sacc[nf][2] = v2; sacc[nf][3] = v3;
            mx0 = fmaxf(mx0, fmaxf(v0, v1));
            mx1 = fmaxf(mx1, fmaxf(v2, v3));
        }
        mx0 = fmaxf(mx0, __shfl_xor_sync(0xffffffffu, mx0, 1));
        mx0 = fmaxf(mx0, __shfl_xor_sync(0xffffffffu, mx0, 2));
        mx1 = fmaxf(mx1, __shfl_xor_sync(0xffffffffu, mx1, 1));
        mx1 = fmaxf(mx1, __shfl_xor_sync(0xffffffffu, mx1, 2));

        float mn0 = fmaxf(m0r, mx0);
        float mn1 = fmaxf(m1r, mx1);
        float corr0 = __expf(m0r - mn0);
        float corr1 = __expf(m1r - mn1);
        m0r = mn0; m1r = mn1;

        float rs0 = 0.0f, rs1 = 0.0f;
#pragma unroll
        for (int nf = 0; nf < 16; nf++) {
            float p0 = __expf(sacc[nf][0] - mn0);
            float p1 = __expf(sacc[nf][1] - mn0);
            float p2 = __expf(sacc[nf][2] - mn1);
            float p3 = __expf(sacc[nf][3] - mn1);
            sacc[nf][0] = p0; sacc[nf][1] = p1; sacc[nf][2] = p2; sacc[nf][3] = p3;
            rs0 += p0 + p1; rs1 += p2 + p3;
        }
        rs0 += __shfl_xor_sync(0xffffffffu, rs0, 1);
        rs0 += __shfl_xor_sync(0xffffffffu, rs0, 2);
        rs1 += __shfl_xor_sync(0xffffffffu, rs1, 1);
        rs1 += __shfl_xor_sync(0xffffffffu, rs1, 2);
        l0 = l0 * corr0 + rs0;
        l1 = l1 * corr1 + rs1;

#pragma unroll
        for (int nf = 0; nf < 8; nf++) {
            oacc[nf][0] *= corr0; oacc[nf][1] *= corr0;
            oacc[nf][2] *= corr1; oacc[nf][3] *= corr1;
        }

        // ---- O += P V (3-pass hi/lo, P packed from registers) ----
#pragma unroll
        for (int ks = 0; ks < 8; ks++) {
            uint32_t pah[4], pal[4];
            float r0, r1;
            pah[0] = packhi(sacc[2*ks][0],   sacc[2*ks][1],   r0, r1); pal[0] = packlo(r0, r1);
            pah[1] = packhi(sacc[2*ks][2],   sacc[2*ks][3],   r0, r1); pal[1] = packlo(r0, r1);
            pah[2] = packhi(sacc[2*ks+1][0], sacc[2*ks+1][1], r0, r1); pal[2] = packlo(r0, r1);
            pah[3] = packhi(sacc[2*ks+1][2], sacc[2*ks+1][3], r0, r1); pal[3] = packlo(r0, r1);
#pragma unroll
            for (int nb = 0; nb < 4; nb++) {
                uint32_t bhx[4], blx[4];
                uint32_t vd = (vElem + (uint32_t)(ks * 16 * AROW) + (uint32_t)(nb * 16)) * 2;
                ldm4t(bhx, vh32 + vd);
                ldm4t(blx, vl32 + vd);
                mma_bf16(oacc[2*nb],   pah, bhx[0], bhx[1]);
                mma_bf16(oacc[2*nb],   pal, bhx[0], bhx[1]);
                mma_bf16(oacc[2*nb],   pah, blx[0], blx[1]);
                mma_bf16(oacc[2*nb+1], pah, bhx[2], bhx[3]);
                mma_bf16(oacc[2*nb+1], pal, bhx[2], bhx[3]);
                mma_bf16(oacc[2*nb+1], pah, blx[2], blx[3]);
            }
        }
    }

    // ---- epilogue: normalize + store to [B, S, D] ----
    const float inv0 = 1.0f / l0;
    const float inv1 = 1.0f / l1;
    float* op = out + (size_t)b * SEQ * DM + (size_t)h * HW;
#pragma unroll
    for (int nf = 0; nf < 8; nf++) {
        int col = nf * 8 + t2;
        *(float2*)(op + (size_t)row0 * DM + col) =
            make_float2(oacc[nf][0] * inv0, oacc[nf][1] * inv0);
        *(float2*)(op + (size_t)row1 * DM + col) =
            make_float2(oacc[nf][2] * inv1, oacc[nf][3] * inv1);
    }
}

// ---------------------------------------------------------------------------
// Launch: inputs order = queries, keys, values, mask, Wq, Wk, Wv.
// ---------------------------------------------------------------------------
extern "C" void kernel_launch(void* const* d_in, const int* in_sizes, int n_in,
                              void* d_out, int out_size)
{
    (void)in_sizes; (void)n_in; (void)out_size;
    const float* q  = (const float*)d_in[0];
    const float* k  = (const float*)d_in[1];
    const float* v  = (const float*)d_in[2];
    const float* wq = (const float*)d_in[4];
    const float* wk = (const float*)d_in[5];
    const float* wv = (const float*)d_in[6];
    float* out = (float*)d_out;

    const int attn_smem = 6 * ATILE * 2;   // 110592 B
    cudaFuncSetAttribute(attn_mma, cudaFuncAttributeMaxDynamicSharedMemorySize, attn_smem);

    proj_mma<<<dim3(DM/128, (BATCH*SEQ)/128, 3), 256>>>(q, k, v, wq, wk, wv);
    attn_mma<<<dim3(SEQ/128, BATCH*NH), 256, attn_smem>>>(out);
}

// round 6
// speedup vs baseline: 2.8082x; 1.6401x over previous
#include <cuda_runtime.h>
#include <cuda_bf16.h>
#include <cstdint>
#include <math.h>

#define BATCH 2
#define SEQ   2048
#define DM    1024
#define NH    16
#define HW    64
#define SM_SCALE 0.125f   // 1/sqrt(64)

#define NELEM (BATCH*NH*SEQ*HW)

// Pre-split bf16 hi/lo planes of projected Q/K/V in [B, H, S, hw] layout.
__device__ __nv_bfloat16 g_qh[NELEM], g_ql[NELEM];
__device__ __nv_bfloat16 g_kh[NELEM], g_kl[NELEM];
__device__ __nv_bfloat16 g_vh[NELEM], g_vl[NELEM];

// ---------------------------------------------------------------------------
// Helpers
// ---------------------------------------------------------------------------
__device__ __forceinline__ uint32_t smem_u32(const void* p) {
    uint32_t a;
    asm("{ .reg .u64 t; cvta.to.shared.u64 t, %1; cvt.u32.u64 %0, t; }"
        : "=r"(a) : "l"(p));
    return a;
}

__device__ __forceinline__ void ldm4(uint32_t r[4], uint32_t addr) {
    asm volatile("ldmatrix.sync.aligned.m8n8.x4.shared.b16 {%0,%1,%2,%3}, [%4];"
                 : "=r"(r[0]), "=r"(r[1]), "=r"(r[2]), "=r"(r[3]) : "r"(addr));
}
__device__ __forceinline__ void ldm4t(uint32_t r[4], uint32_t addr) {
    asm volatile("ldmatrix.sync.aligned.m8n8.x4.trans.shared.b16 {%0,%1,%2,%3}, [%4];"
                 : "=r"(r[0]), "=r"(r[1]), "=r"(r[2]), "=r"(r[3]) : "r"(addr));
}

__device__ __forceinline__ void mma_bf16(float acc[4], const uint32_t a[4],
                                         uint32_t b0, uint32_t b1) {
    asm volatile(
        "mma.sync.aligned.m16n8k16.row.col.f32.bf16.bf16.f32 "
        "{%0,%1,%2,%3}, {%4,%5,%6,%7}, {%8,%9}, {%0,%1,%2,%3};"
        : "+f"(acc[0]), "+f"(acc[1]), "+f"(acc[2]), "+f"(acc[3])
        : "r"(a[0]), "r"(a[1]), "r"(a[2]), "r"(a[3]), "r"(b0), "r"(b1));
}

__device__ __forceinline__ uint32_t packhi(float a, float b, float& ra, float& rb) {
    __nv_bfloat16 ha = __float2bfloat16(a);
    __nv_bfloat16 hb = __float2bfloat16(b);
    ra = a - __bfloat162float(ha);
    rb = b - __bfloat162float(hb);
    return (uint32_t)__bfloat16_as_ushort(ha) |
           ((uint32_t)__bfloat16_as_ushort(hb) << 16);
}
__device__ __forceinline__ uint32_t packlo(float a, float b) {
    return (uint32_t)__bfloat16_as_ushort(__float2bfloat16(a)) |
           ((uint32_t)__bfloat16_as_ushort(__float2bfloat16(b)) << 16);
}

__device__ __forceinline__ void cpa16(uint32_t saddr, const void* g) {
    asm volatile("cp.async.cg.shared.global [%0], [%1], 16;"
                 :: "r"(saddr), "l"(g) : "memory");
}
#define CPA_COMMIT() asm volatile("cp.async.commit_group;" ::: "memory")
#define CPA_WAIT0()  asm volatile("cp.async.wait_group 0;" ::: "memory")

// ---------------------------------------------------------------------------
// Projection GEMM on mma.sync bf16 (hi/lo 3-pass). Epilogue writes bf16
// hi/lo planes directly (attention consumes bf16; no fp32 scratch).
// ---------------------------------------------------------------------------
#define SROW 40

__global__ __launch_bounds__(256) void proj_mma(
    const float* __restrict__ xq, const float* __restrict__ xk, const float* __restrict__ xv,
    const float* __restrict__ wq, const float* __restrict__ wk, const float* __restrict__ wv)
{
    __shared__ __align__(16) unsigned short sAh[128*SROW];
    __shared__ __align__(16) unsigned short sAl[128*SROW];
    __shared__ __align__(16) unsigned short sBh[128*SROW];
    __shared__ __align__(16) unsigned short sBl[128*SROW];

    const int z = blockIdx.z;
    const float* X = (z == 0) ? xq : (z == 1) ? xk : xv;
    const float* W = (z == 0) ? wq : (z == 1) ? wk : wv;
    __nv_bfloat16* Oh = (z == 0) ? g_qh : (z == 1) ? g_kh : g_vh;
    __nv_bfloat16* Ol = (z == 0) ? g_ql : (z == 1) ? g_kl : g_vl;

    const int tid   = threadIdx.x;
    const int wid   = tid >> 5;
    const int lane  = tid & 31;
    const int warpM = wid >> 1;
    const int warpN = wid & 1;
    const int m0    = blockIdx.y * 128;
    const int n0    = blockIdx.x * 128;

    const float4* X4 = (const float4*)X;
    const float4* W4 = (const float4*)W;

    const uint32_t sAh32 = smem_u32(sAh), sAl32 = smem_u32(sAl);
    const uint32_t sBh32 = smem_u32(sBh), sBl32 = smem_u32(sBl);
    const uint32_t aRow = (uint32_t)(warpM * 32 + (lane & 15));
    const uint32_t aCol = (uint32_t)((lane >> 4) << 3);
    const uint32_t aOff = (aRow * SROW + aCol) * 2;
    const uint32_t bRow = (uint32_t)(warpN * 64 + (lane & 7) + ((lane >> 4) << 3));
    const uint32_t bCol = (uint32_t)(((lane >> 3) & 1) << 3);
    const uint32_t bOff = (bRow * SROW + bCol) * 2;

    float acc[2][8][4];
#pragma unroll
    for (int mf = 0; mf < 2; mf++)
#pragma unroll
        for (int nf = 0; nf < 8; nf++)
#pragma unroll
            for (int i = 0; i < 4; i++) acc[mf][nf][i] = 0.0f;

    const int row = tid >> 3;
    const int cg  = tid & 7;

    float4 pa[4], pb[4];
#pragma unroll
    for (int t = 0; t < 4; t++) {
        int r = row + t * 32;
        pa[t] = X4[(size_t)(m0 + r) * 256 + cg];
        pb[t] = W4[(size_t)(n0 + r) * 256 + cg];
    }

    for (int c = 0; c < 32; c++) {
        if (c) __syncthreads();

#pragma unroll
        for (int t = 0; t < 4; t++) {
            int r   = row + t * 32;
            int idx = r * SROW + cg * 4;
            float r0, r1, r2, r3;
            uint32_t h01 = packhi(pa[t].x, pa[t].y, r0, r1);
            uint32_t h23 = packhi(pa[t].z, pa[t].w, r2, r3);
            *(uint2*)(sAh + idx) = make_uint2(h01, h23);
            *(uint2*)(sAl + idx) = make_uint2(packlo(r0, r1), packlo(r2, r3));
            h01 = packhi(pb[t].x, pb[t].y, r0, r1);
            h23 = packhi(pb[t].z, pb[t].w, r2, r3);
            *(uint2*)(sBh + idx) = make_uint2(h01, h23);
            *(uint2*)(sBl + idx) = make_uint2(packlo(r0, r1), packlo(r2, r3));
        }
        __syncthreads();

        if (c < 31) {
#pragma unroll
            for (int t = 0; t < 4; t++) {
                int r = row + t * 32;
                pa[t] = X4[(size_t)(m0 + r) * 256 + (c + 1) * 8 + cg];
                pb[t] = W4[(size_t)(n0 + r) * 256 + (c + 1) * 8 + cg];
            }
        }

#pragma unroll
        for (int ks = 0; ks < 2; ks++) {
            const uint32_t kByte = (uint32_t)(ks * 32);
            uint32_t ah[2][4], al[2][4], bh[4][4], bl[4][4];
#pragma unroll
            for (int mf = 0; mf < 2; mf++) {
                uint32_t ad = aOff + (uint32_t)(mf * 16 * SROW * 2) + kByte;
                ldm4(ah[mf], sAh32 + ad);
                ldm4(al[mf], sAl32 + ad);
            }
#pragma unroll
            for (int p = 0; p < 4; p++) {
                uint32_t bd = bOff + (uint32_t)(p * 16 * SROW * 2) + kByte;
                ldm4(bh[p], sBh32 + bd);
                ldm4(bl[p], sBl32 + bd);
            }
#pragma unroll
            for (int mf = 0; mf < 2; mf++)
#pragma unroll
                for (int nf = 0; nf < 8; nf++) {
                    const int p = nf >> 1, q = (nf & 1) * 2;
                    mma_bf16(acc[mf][nf], ah[mf], bh[p][q], bh[p][q+1]);
                    mma_bf16(acc[mf][nf], al[mf], bh[p][q], bh[p][q+1]);
                    mma_bf16(acc[mf][nf], ah[mf], bl[p][q], bl[p][q+1]);
                }
        }
    }

    // Epilogue: split fp32 acc -> bf16 hi/lo planes, [B, H, S, hw] layout.
    const int g  = lane >> 2;
    const int t2 = (lane & 3) << 1;
#pragma unroll
    for (int mf = 0; mf < 2; mf++) {
        int mA  = m0 + warpM * 32 + mf * 16 + g;
        int mB  = mA + 8;
        int bbA = mA >> 11, ssA = mA & (SEQ - 1);
        int bbB = mB >> 11, ssB = mB & (SEQ - 1);
#pragma unroll
        for (int nf = 0; nf < 8; nf++) {
            int n  = n0 + warpN * 64 + nf * 8 + t2;
            int hh = n >> 6, dd = n & 63;
            size_t offA = (((size_t)(bbA * NH + hh)) * SEQ + ssA) * HW + dd;
            size_t offB = (((size_t)(bbB * NH + hh)) * SEQ + ssB) * HW + dd;
            float r0, r1;
            uint32_t hp = packhi(acc[mf][nf][0], acc[mf][nf][1], r0, r1);
            *(uint32_t*)(Oh + offA) = hp;
            *(uint32_t*)(Ol + offA) = packlo(r0, r1);
            hp = packhi(acc[mf][nf][2], acc[mf][nf][3], r0, r1);
            *(uint32_t*)(Oh + offB) = hp;
            *(uint32_t*)(Ol + offB) = packlo(r0, r1);
        }
    }
}

// ---------------------------------------------------------------------------
// Flash attention on mma.sync bf16 (hi/lo 3-pass), causal + ALiBi.
// Inputs are pre-split bf16 hi/lo planes; K/V double-buffered via cp.async.
// Block = 128 q-rows, 8 warps; warp w owns q-rows [16w,16w+16).
// smem: Qh,Ql + 2 x (Kh,Kl,Vh,Vl) = 10 tiles x 18432 B = 184320 B.
// ---------------------------------------------------------------------------
#define AROW 72
#define ATILE (128*AROW)       // bf16 elements per tile
#define TB    (ATILE*2)        // bytes per tile

__device__ __forceinline__ void tile_async(uint32_t sbase, const __nv_bfloat16* g,
                                           int row0, int tid) {
#pragma unroll
    for (int t = 0; t < 4; t++) {
        int i  = tid + t * 256;       // 0..1023
        int r  = i >> 3, c8 = i & 7;
        cpa16(sbase + (uint32_t)(r * AROW + c8 * 8) * 2,
              g + (size_t)(row0 + r) * HW + c8 * 8);
    }
}

__global__ __launch_bounds__(256, 1) void attn_mma(float* __restrict__ out)
{
    extern __shared__ unsigned short asm_[];
    const uint32_t base = smem_u32(asm_);
    const uint32_t qh32 = base;
    const uint32_t ql32 = base + TB;
    // buffer p tiles: Kh, Kl, Vh, Vl at base + (2 + 4p + idx)*TB

    const int bh = blockIdx.y;
    const int b  = bh >> 4;
    const int h  = bh & 15;
    const int qt = (int)gridDim.x - 1 - (int)blockIdx.x;  // heavy tiles first
    const int q0 = qt * 128;

    const int tid  = threadIdx.x;
    const int warp = tid >> 5;
    const int lane = tid & 31;
    const int g    = lane >> 2;
    const int t2   = (lane & 3) << 1;

    const float slope = exp2f(-0.5f * (float)(h + 1));

    const __nv_bfloat16* Qh = g_qh + (size_t)bh * SEQ * HW;
    const __nv_bfloat16* Ql = g_ql + (size_t)bh * SEQ * HW;
    const __nv_bfloat16* Kh = g_kh + (size_t)bh * SEQ * HW;
    const __nv_bfloat16* Kl = g_kl + (size_t)bh * SEQ * HW;
    const __nv_bfloat16* Vh = g_vh + (size_t)bh * SEQ * HW;
    const __nv_bfloat16* Vl = g_vl + (size_t)bh * SEQ * HW;

    // ---- load Q tile (plain copies) ----
#pragma unroll
    for (int t = 0; t < 4; t++) {
        int i = tid + t * 256;
        int r = i >> 3, c8 = i & 7;
        uint32_t soff = (uint32_t)(r * AROW + c8 * 8) * 2;
        *(uint4*)((char*)asm_ + (qh32 - base) + soff) =
            *(const uint4*)(Qh + (size_t)(q0 + r) * HW + c8 * 8);
        *(uint4*)((char*)asm_ + (ql32 - base) + soff) =
            *(const uint4*)(Ql + (size_t)(q0 + r) * HW + c8 * 8);
    }

    // ---- preload k-tile 0 into buffer 0 ----
    {
        uint32_t b0 = base + 2 * TB;
        tile_async(b0 + 0 * TB, Kh, 0, tid);
        tile_async(b0 + 1 * TB, Kl, 0, tid);
        tile_async(b0 + 2 * TB, Vh, 0, tid);
        tile_async(b0 + 3 * TB, Vl, 0, tid);
        CPA_COMMIT();
    }

    // ldmatrix element offsets (within a tile)
    const uint32_t aElem = (uint32_t)((warp * 16 + (lane & 15)) * AROW + ((lane >> 4) << 3));
    const uint32_t bElem = (uint32_t)(((lane & 7) + ((lane >> 4) << 3)) * AROW + (((lane >> 3) & 1) << 3));
    const uint32_t vElem = (uint32_t)((lane & 15) * AROW + ((lane >> 4) << 3));

    float oacc[8][4];
#pragma unroll
    for (int nf = 0; nf < 8; nf++)
#pragma unroll
        for (int e = 0; e < 4; e++) oacc[nf][e] = 0.0f;

    float m0r = -3e38f, m1r = -3e38f, l0 = 0.0f, l1 = 0.0f;
    const int row0 = q0 + warp * 16 + g;
    const int row1 = row0 + 8;

    for (int kt = 0; kt <= qt; kt++) {
        const int p = kt & 1;
        CPA_WAIT0();
        __syncthreads();

        if (kt < qt) {
            uint32_t bn = base + (2 + 4 * (p ^ 1)) * TB;
            int r0n = (kt + 1) * 128;
            tile_async(bn + 0 * TB, Kh, r0n, tid);
            tile_async(bn + 1 * TB, Kl, r0n, tid);
            tile_async(bn + 2 * TB, Vh, r0n, tid);
            tile_async(bn + 3 * TB, Vl, r0n, tid);
            CPA_COMMIT();
        }

        const uint32_t kh32 = base + (2 + 4 * p + 0) * TB;
        const uint32_t kl32 = base + (2 + 4 * p + 1) * TB;
        const uint32_t vh32 = base + (2 + 4 * p + 2) * TB;
        const uint32_t vl32 = base + (2 + 4 * p + 3) * TB;
        const int k0g = kt * 128;

        // ---- S = Q K^T (3-pass hi/lo) ----
        float sacc[16][4];
#pragma unroll
        for (int nf = 0; nf < 16; nf++)
#pragma unroll
            for (int e = 0; e < 4; e++) sacc[nf][e] = 0.0f;

#pragma unroll
        for (int ks = 0; ks < 4; ks++) {
            uint32_t ah[4], al[4];
            ldm4(ah, qh32 + (aElem + ks * 16) * 2);
            ldm4(al, ql32 + (aElem + ks * 16) * 2);
#pragma unroll
            for (int pp = 0; pp < 8; pp++) {
                uint32_t bhx[4], blx[4];
                uint32_t bd = (bElem + (uint32_t)(pp * 16 * AROW) + (uint32_t)(ks * 16)) * 2;
                ldm4(bhx, kh32 + bd);
                ldm4(blx, kl32 + bd);
                mma_bf16(sacc[2*pp],   ah, bhx[0], bhx[1]);
                mma_bf16(sacc[2*pp],   al, bhx[0], bhx[1]);
                mma_bf16(sacc[2*pp],   ah, blx[0], blx[1]);
                mma_bf16(sacc[2*pp+1], ah, bhx[2], bhx[3]);
                mma_bf16(sacc[2*pp+1], al, bhx[2], bhx[3]);
                mma_bf16(sacc[2*pp+1], ah, blx[2], blx[3]);
            }
        }

        // ---- scale + ALiBi + causal; online softmax ----
        const bool diag = (kt == qt);
        float mx0 = -3e38f, mx1 = -3e38f;
#pragma unroll
        for (int nf = 0; nf < 16; nf++) {
            int c0 = k0g + nf * 8 + t2;
            int c1 = c0 + 1;
            float v0 = sacc[nf][0] * SM_SCALE + slope * (float)(c0 - row0);
            float v1 = sacc[nf][1] * SM_SCALE + slope * (float)(c1 - row0);
            float v2 = sacc[nf][2] * SM_SCALE + slope * (float)(c0 - row1);
            float v3 = sacc[nf][3] * SM_SCALE + slope * (float)(c1 - row1);
            if (diag) {
                if (c0 > row0) v0 = -3e38f;
                if (c1 > row0) v1 = -3e38f;
                if (c0 > row1) v2 = -3e38f;
                if (c1 > row1) v3 = -3e38f;
            }
            sacc[nf][0] = v0; sacc[nf][1] = v1; sacc[nf][2] = v2; sacc[nf][3] = v3;
            mx0 = fmaxf(mx0, fmaxf(v0, v1));
            mx1 = fmaxf(mx1, fmaxf(v2, v3));
        }
        mx0 = fmaxf(mx0, __shfl_xor_sync(0xffffffffu, mx0, 1));
        mx0 = fmaxf(mx0, __shfl_xor_sync(0xffffffffu, mx0, 2));
        mx1 = fmaxf(mx1, __shfl_xor_sync(0xffffffffu, mx1, 1));
        mx1 = fmaxf(mx1, __shfl_xor_sync(0xffffffffu, mx1, 2));

        float mn0 = fmaxf(m0r, mx0);
        float mn1 = fmaxf(m1r, mx1);
        float corr0 = __expf(m0r - mn0);
        float corr1 = __expf(m1r - mn1);
        m0r = mn0; m1r = mn1;

        float rs0 = 0.0f, rs1 = 0.0f;
#pragma unroll
        for (int nf = 0; nf < 16; nf++) {
            float p0 = __expf(sacc[nf][0] - mn0);
            float p1 = __expf(sacc[nf][1] - mn0);
            float p2 = __expf(sacc[nf][2] - mn1);
            float p3 = __expf(sacc[nf][3] - mn1);
            sacc[nf][0] = p0; sacc[nf][1] = p1; sacc[nf][2] = p2; sacc[nf][3] = p3;
            rs0 += p0 + p1; rs1 += p2 + p3;
        }
        rs0 += __shfl_xor_sync(0xffffffffu, rs0, 1);
        rs0 += __shfl_xor_sync(0xffffffffu, rs0, 2);
        rs1 += __shfl_xor_sync(0xffffffffu, rs1, 1);
        rs1 += __shfl_xor_sync(0xffffffffu, rs1, 2);
        l0 = l0 * corr0 + rs0;
        l1 = l1 * corr1 + rs1;

#pragma unroll
        for (int nf = 0; nf < 8; nf++) {
            oacc[nf][0] *= corr0; oacc[nf][1] *= corr0;
            oacc[nf][2] *= corr1; oacc[nf][3] *= corr1;
        }

        // ---- O += P V (3-pass hi/lo, P packed from registers) ----
#pragma unroll
        for (int ks = 0; ks < 8; ks++) {
            uint32_t pah[4], pal[4];
            float r0, r1;
            pah[0] = packhi(sacc[2*ks][0],   sacc[2*ks][1],   r0, r1); pal[0] = packlo(r0, r1);
            pah[1] = packhi(sacc[2*ks][2],   sacc[2*ks][3],   r0, r1); pal[1] = packlo(r0, r1);
            pah[2] = packhi(sacc[2*ks+1][0], sacc[2*ks+1][1], r0, r1); pal[2] = packlo(r0, r1);
            pah[3] = packhi(sacc[2*ks+1][2], sacc[2*ks+1][3], r0, r1); pal[3] = packlo(r0, r1);
#pragma unroll
            for (int nb = 0; nb < 4; nb++) {
                uint32_t bhx[4], blx[4];
                uint32_t vd = (vElem + (uint32_t)(ks * 16 * AROW) + (uint32_t)(nb * 16)) * 2;
                ldm4t(bhx, vh32 + vd);
                ldm4t(blx, vl32 + vd);
                mma_bf16(oacc[2*nb],   pah, bhx[0], bhx[1]);
                mma_bf16(oacc[2*nb],   pal, bhx[0], bhx[1]);
                mma_bf16(oacc[2*nb],   pah, blx[0], blx[1]);
                mma_bf16(oacc[2*nb+1], pah, bhx[2], bhx[3]);
                mma_bf16(oacc[2*nb+1], pal, bhx[2], bhx[3]);
                mma_bf16(oacc[2*nb+1], pah, blx[2], blx[3]);
            }
        }
    }

    // ---- epilogue: normalize + store to [B, S, D] ----
    const float inv0 = 1.0f / l0;
    const float inv1 = 1.0f / l1;
    float* op = out + (size_t)b * SEQ * DM + (size_t)h * HW;
#pragma unroll
    for (int nf = 0; nf < 8; nf++) {
        int col = nf * 8 + t2;
        *(float2*)(op + (size_t)row0 * DM + col) =
            make_float2(oacc[nf][0] * inv0, oacc[nf][1] * inv0);
        *(float2*)(op + (size_t)row1 * DM + col) =
            make_float2(oacc[nf][2] * inv1, oacc[nf][3] * inv1);
    }
}

// ---------------------------------------------------------------------------
// Launch: inputs order = queries, keys, values, mask, Wq, Wk, Wv.
// ---------------------------------------------------------------------------
extern "C" void kernel_launch(void* const* d_in, const int* in_sizes, int n_in,
                              void* d_out, int out_size)
{
    (void)in_sizes; (void)n_in; (void)out_size;
    const float* q  = (const float*)d_in[0];
    const float* k  = (const float*)d_in[1];
    const float* v  = (const float*)d_in[2];
    const float* wq = (const float*)d_in[4];
    const float* wk = (const float*)d_in[5];
    const float* wv = (const float*)d_in[6];
    float* out = (float*)d_out;

    const int attn_smem = 10 * TB;   // 184320 B
    cudaFuncSetAttribute(attn_mma, cudaFuncAttributeMaxDynamicSharedMemorySize, attn_smem);

    proj_mma<<<dim3(DM/128, (BATCH*SEQ)/128, 3), 256>>>(q, k, v, wq, wk, wv);
    attn_mma<<<dim3(SEQ/128, BATCH*NH), 256, attn_smem>>>(out);
}